// round 14
// baseline (speedup 1.0000x reference)
#include <cuda_runtime.h>
#include <cuda_fp16.h>
#include <cstdint>
#include <math.h>

// ---------------------------------------------------------------------------
// MultiViewTripletLoss: dist(x,y)=sqrt(2-2 x.y) for unit vectors; hard-negative
// mining == masked row-max of dot products.  Single fp16 GEMM (K=256),
// mma.sync.m16n8k16, 128x128 tiles, 2 CTAs/SM, flip-encoded atomicMax partial
// maxima, A.A^T triangular symmetry with column-max scatter.
// R14 = identical resubmission of R13 (container infra failed twice; kernel
// never ran).  R13 = R9's proven pipeline (3 buffers, wait(1), two barriers/
// stage) + fused last-CTA finalize tail (kills one launch).
// ---------------------------------------------------------------------------

#define BB    4096
#define DD    256
#define NSTG  8            // K stages (256/32)
#define PITCH 80           // smem row pitch bytes (64 data + 16 pad)
#define NTRI  528          // upper-tri tiles for matrix 0 (32*33/2)
#define NBLK  (NTRI + 2 * 1024)

__device__ __align__(16) __half g_X[(size_t)3 * BB * DD];   // [m][row][k]
__device__ unsigned int g_negbits[3 * BB];   // flip-encoded row maxima
__device__ float g_pos[2 * BB];              // positive-pair dots
__device__ int g_cnt;                        // completion counter (self-reset)

// smem: labc[128] @0 | labr[128] @512 | stages @1024 (3 x 20480)
#define SM_LABC 0
#define SM_LABR 512
#define SM_STG  1024
#define STG_SZ  20480
#define SM_A(b) (SM_STG + (b) * STG_SZ)
#define SM_B(b) (SM_A(b) + 10240)
#define SMEM_TOTAL (SM_STG + 3 * STG_SZ)     // 62464

__device__ __forceinline__ uint32_t smem_u32(const void* p) {
    uint32_t a;
    asm("{ .reg .u64 t; cvta.to.shared.u64 t, %1; cvt.u32.u64 %0, t; }"
        : "=r"(a) : "l"(p));
    return a;
}
#define CP16(dst, src) \
    asm volatile("cp.async.cg.shared.global [%0], [%1], 16;" :: "r"(dst), "l"(src))
#define CP_COMMIT() asm volatile("cp.async.commit_group;" ::: "memory")
#define CP_WAIT(n)  asm volatile("cp.async.wait_group %0;" :: "n"(n) : "memory")
#define LDM4(r, a) \
    asm volatile("ldmatrix.sync.aligned.m8n8.x4.shared.b16 {%0,%1,%2,%3}, [%4];" \
        : "=r"((r)[0]), "=r"((r)[1]), "=r"((r)[2]), "=r"((r)[3]) : "r"(a))
#define MMA(d, a, b0, b1) \
    asm volatile("mma.sync.aligned.m16n8k16.row.col.f32.f16.f16.f32 " \
        "{%0,%1,%2,%3}, {%4,%5,%6,%7}, {%8,%9}, {%0,%1,%2,%3};" \
        : "+f"((d)[0]), "+f"((d)[1]), "+f"((d)[2]), "+f"((d)[3]) \
        : "r"((a)[0]), "r"((a)[1]), "r"((a)[2]), "r"((a)[3]), "r"(b0), "r"(b1))

// monotone float <-> uint encoding for atomicMax over signed floats
__device__ __forceinline__ unsigned int fflip(float f) {
    unsigned int u = __float_as_uint(f);
    return u ^ (unsigned int)(((int)u >> 31) | 0x80000000);
}
__device__ __forceinline__ float funflip(unsigned int m) {
    unsigned int u = (m & 0x80000000u) ? (m ^ 0x80000000u) : ~m;
    return __uint_as_float(u);
}

// --------------------------- normalize -> fp16 (+ negbits init) ------------
__global__ void norm_kernel(const float* __restrict__ anchor,
                            const float* __restrict__ positive) {
    int warp = (blockIdx.x * blockDim.x + threadIdx.x) >> 5;
    int lane = threadIdx.x & 31;
    if (warp >= 3 * BB) return;
    if (lane == 0) g_negbits[warp] = 0u;     // == fflip(very negative)

    const float* src;
    __half2* dst;
    if (warp < BB) {
        src = anchor + (size_t)warp * DD;
        dst = (__half2*)(g_X + (size_t)warp * DD);
    } else {
        int r = warp - BB, i = r >> 1, v = r & 1;   // r = i*2 + v
        src = positive + (size_t)r * DD;
        dst = (__half2*)(g_X + (size_t)((1 + v) * BB + i) * DD);
    }

    const float4* s4 = (const float4*)src;
    float4 x0 = s4[lane], x1 = s4[lane + 32];
    float ss = x0.x*x0.x + x0.y*x0.y + x0.z*x0.z + x0.w*x0.w
             + x1.x*x1.x + x1.y*x1.y + x1.z*x1.z + x1.w*x1.w;
    #pragma unroll
    for (int o = 16; o >= 1; o >>= 1) ss += __shfl_xor_sync(0xffffffffu, ss, o);
    float inv = rsqrtf(fmaxf(ss, 1e-24f));

    dst[2*lane]      = __floats2half2_rn(x0.x*inv, x0.y*inv);
    dst[2*lane + 1]  = __floats2half2_rn(x0.z*inv, x0.w*inv);
    dst[64 + 2*lane] = __floats2half2_rn(x1.x*inv, x1.y*inv);
    dst[65 + 2*lane] = __floats2half2_rn(x1.z*inv, x1.w*inv);
}

// --------------------------- GEMM + masked max (row & col) -----------------
__device__ __forceinline__ void load_stage(uint32_t sb, int buf, int s,
                                           int rowbase, int brow, int tid) {
    const char* Xg = (const char*)g_X;
    #pragma unroll
    for (int lp = 0; lp < 2; lp++) {                 // A: 512 chunks of 16B
        int idx = tid + (lp << 8);
        int row = idx >> 2, ch = idx & 3;
        uint32_t dst = sb + SM_A(buf) + row * PITCH + ch * 16;
        const char* src = Xg + (size_t)(rowbase + row) * (DD * 2) + s * 64 + ch * 16;
        CP16(dst, src);
    }
    #pragma unroll
    for (int lp = 0; lp < 2; lp++) {                 // B: 512 chunks of 16B
        int idx = tid + (lp << 8);
        int row = idx >> 2, ch = idx & 3;
        uint32_t dst = sb + SM_B(buf) + row * PITCH + ch * 16;
        const char* src = Xg + (size_t)(brow + row) * (DD * 2) + s * 64 + ch * 16;
        CP16(dst, src);
    }
    CP_COMMIT();
}

__global__ __launch_bounds__(256, 2)
void gemm_max_kernel(const int* __restrict__ labels, float* __restrict__ out) {
    extern __shared__ char smem[];
    uint32_t sb = smem_u32(smem);
    int* labc = (int*)(smem + SM_LABC);
    int* labr = (int*)(smem + SM_LABR);

    const int tid = threadIdx.x;
    const int lane = tid & 31;
    const int wid = tid >> 5;
    const int wm = wid >> 2, wn = wid & 3;           // 2 x 4 warp grid

    // ---- decode (m, rt, ct) from linear block id (closed form) ----
    int bid = blockIdx.x;
    int m, rt, ct;
    if (bid < NTRI) {
        m = 0;
        float bf = (float)bid;
        int r = (int)floorf(32.5f - sqrtf(32.5f * 32.5f - 2.0f * bf));
        int off = (r * (65 - r)) >> 1;
        if (off > bid)          { r--; off = (r * (65 - r)) >> 1; }
        else if (off + (32 - r) <= bid) { r++; off = (r * (65 - r)) >> 1; }
        rt = r;
        ct = r + (bid - off);
    } else {
        int t = bid - NTRI;
        m = 1 + (t >> 10);
        rt = (t & 1023) >> 5;
        ct = t & 31;
    }
    const int rowbase = rt << 7;
    const int cibase  = ct << 7;                     // col base within matrix
    const int brow    = m * BB + cibase;             // B rows in g_X

    if (tid < 128) {
        labc[tid] = labels[cibase + tid];
        labr[tid] = labels[rowbase + tid];
    }

    float acc[4][4][4];                              // [mi][ni][frag]
    #pragma unroll
    for (int i = 0; i < 4; i++)
        #pragma unroll
        for (int j = 0; j < 4; j++)
            #pragma unroll
            for (int k = 0; k < 4; k++) acc[i][j][k] = 0.f;

    load_stage(sb, 0, 0, rowbase, brow, tid);
    load_stage(sb, 1, 1, rowbase, brow, tid);

    // warp tile 64x32: A rows wm*64 + mi*16, B cols wn*32 + ni2*16
    const uint32_t a_off = (wm * 64 + (lane & 15)) * PITCH + ((lane >> 4) & 1) * 16;
    const uint32_t b_off = (wn * 32 + (lane & 7) + ((lane >> 4) & 1) * 8) * PITCH
                         + ((lane >> 3) & 1) * 16;

    for (int s = 0; s < NSTG; s++) {
        int buf = s % 3;
        CP_WAIT(1);
        __syncthreads();

        uint32_t ab = sb + SM_A(buf) + a_off;
        uint32_t bb = sb + SM_B(buf) + b_off;
        #pragma unroll
        for (int ks = 0; ks < 2; ks++) {
            uint32_t af[4][4];
            #pragma unroll
            for (int mi = 0; mi < 4; mi++)
                LDM4(af[mi], ab + ks * 32 + mi * 16 * PITCH);
            #pragma unroll
            for (int ni2 = 0; ni2 < 2; ni2++) {
                uint32_t bf[4];
                LDM4(bf, bb + ks * 32 + ni2 * 16 * PITCH);
                #pragma unroll
                for (int mi = 0; mi < 4; mi++) {
                    MMA(acc[mi][2*ni2],   af[mi], bf[0], bf[1]);
                    MMA(acc[mi][2*ni2+1], af[mi], bf[2], bf[3]);
                }
            }
        }
        __syncthreads();
        if (s + 2 < NSTG)
            load_stage(sb, (s + 2) % 3, s + 2, rowbase, brow, tid);
    }

    // ------- epilogue 1: per-row masked max (+ diagonal positives) ---------
    #pragma unroll
    for (int mi = 0; mi < 4; mi++) {
        #pragma unroll
        for (int hi = 0; hi < 2; hi++) {
            int lr = wm * 64 + mi * 16 + hi * 8 + (lane >> 2);
            int rlab = labr[lr];
            int grow = rowbase + lr;
            float mx = -1e30f, pv = 0.f;
            int match = 0;
            #pragma unroll
            for (int ni = 0; ni < 4; ni++) {
                int c = wn * 32 + ni * 8 + 2 * (lane & 3);
                float v0 = acc[mi][ni][hi * 2 + 0];
                float v1 = acc[mi][ni][hi * 2 + 1];
                if (labc[c]     != rlab) mx = fmaxf(mx, v0);
                if (labc[c + 1] != rlab) mx = fmaxf(mx, v1);
                if (m > 0) {
                    if (cibase + c == grow)     { pv += v0; match = 1; }
                    if (cibase + c + 1 == grow) { pv += v1; match = 1; }
                }
            }
            mx = fmaxf(mx, __shfl_xor_sync(0xffffffffu, mx, 1));
            mx = fmaxf(mx, __shfl_xor_sync(0xffffffffu, mx, 2));
            pv += __shfl_xor_sync(0xffffffffu, pv, 1);
            pv += __shfl_xor_sync(0xffffffffu, pv, 2);
            match |= __shfl_xor_sync(0xffffffffu, match, 1);
            match |= __shfl_xor_sync(0xffffffffu, match, 2);
            if ((lane & 3) == 0) {
                atomicMax(&g_negbits[m * BB + grow], fflip(mx));
                if (m > 0 && match) g_pos[(m - 1) * BB + grow] = pv;
            }
        }
    }

    // ------- epilogue 2 (m=0 off-diagonal): per-column masked max ----------
    if (m == 0 && rt != ct) {
        #pragma unroll
        for (int ni = 0; ni < 4; ni++) {
            int c = wn * 32 + ni * 8 + 2 * (lane & 3);
            int cl0 = labc[c], cl1 = labc[c + 1];
            float cm0 = -1e30f, cm1 = -1e30f;
            #pragma unroll
            for (int mi = 0; mi < 4; mi++) {
                #pragma unroll
                for (int hi = 0; hi < 2; hi++) {
                    int lr = wm * 64 + mi * 16 + hi * 8 + (lane >> 2);
                    int rl = labr[lr];
                    float v0 = acc[mi][ni][hi * 2 + 0];
                    float v1 = acc[mi][ni][hi * 2 + 1];
                    if (rl != cl0) cm0 = fmaxf(cm0, v0);
                    if (rl != cl1) cm1 = fmaxf(cm1, v1);
                }
            }
            #pragma unroll
            for (int o = 4; o <= 16; o <<= 1) {
                cm0 = fmaxf(cm0, __shfl_xor_sync(0xffffffffu, cm0, o));
                cm1 = fmaxf(cm1, __shfl_xor_sync(0xffffffffu, cm1, o));
            }
            if (lane < 4) {
                atomicMax(&g_negbits[cibase + c],     fflip(cm0));
                atomicMax(&g_negbits[cibase + c + 1], fflip(cm1));
            }
        }
    }

    // ------- tail: last CTA computes the loss (fused finalize) -------------
    __threadfence();
    __syncthreads();
    __shared__ int s_last;
    if (tid == 0) s_last = (atomicAdd(&g_cnt, 1) == NBLK - 1);
    __syncthreads();
    if (!s_last) return;
    __threadfence();

    float* rs = (float*)smem;                 // labels no longer needed
    float tot = 0.f;
    #pragma unroll
    for (int r = 0; r < 16; r++) {
        int i = tid + (r << 8);
        float ma = funflip(__ldcg(&g_negbits[i]));
        float m0 = funflip(__ldcg(&g_negbits[BB + i]));
        float m1 = funflip(__ldcg(&g_negbits[2 * BB + i]));
        float d0 = __ldcg(&g_pos[i]), d1 = __ldcg(&g_pos[BB + i]);
        float neg0 = sqrtf(fmaxf(2.f - 2.f * fmaxf(ma, m0), 1e-12f));
        float neg1 = sqrtf(fmaxf(2.f - 2.f * fmaxf(ma, m1), 1e-12f));
        float pos0 = sqrtf(fmaxf(2.f - 2.f * d0, 1e-12f));
        float pos1 = sqrtf(fmaxf(2.f - 2.f * d1, 1e-12f));
        tot += fmaxf(pos0 - neg0 + 1.0f, 0.0f) + fmaxf(pos1 - neg1 + 1.0f, 0.0f);
    }
    __syncthreads();                          // everyone past label reads
    rs[tid] = tot;
    __syncthreads();
    #pragma unroll
    for (int o = 128; o >= 1; o >>= 1) {
        if (tid < o) rs[tid] += rs[tid + o];
        __syncthreads();
    }
    if (tid == 0) {
        out[0] = rs[0] * (1.0f / (2.0f * BB));
        g_cnt = 0;                            // reset for next graph replay
    }
}

// ---------------------------------------------------------------------------
extern "C" void kernel_launch(void* const* d_in, const int* in_sizes, int n_in,
                              void* d_out, int out_size) {
    const float* anchor = nullptr;
    const float* positive = nullptr;
    const int*   labels = nullptr;
    for (int i = 0; i < n_in; i++) {
        if (in_sizes[i] == BB * DD)          anchor   = (const float*)d_in[i];
        else if (in_sizes[i] == 2 * BB * DD) positive = (const float*)d_in[i];
        else if (in_sizes[i] == BB)          labels   = (const int*)d_in[i];
    }

    norm_kernel<<<1536, 256>>>(anchor, positive);

    cudaFuncSetAttribute(gemm_max_kernel,
                         cudaFuncAttributeMaxDynamicSharedMemorySize, SMEM_TOTAL);
    gemm_max_kernel<<<NBLK, 256, SMEM_TOTAL>>>(labels, (float*)d_out);
}

// round 15
// speedup vs baseline: 1.2427x; 1.2427x over previous
#include <cuda_runtime.h>
#include <cuda_fp16.h>
#include <cstdint>
#include <math.h>

// ---------------------------------------------------------------------------
// MultiViewTripletLoss: dist(x,y)=sqrt(2-2 x.y) for unit vectors; hard-negative
// mining == masked row-max of dot products.  Single fp16 GEMM (K=256),
// mma.sync.m16n8k16, 128x128 tiles, 2 CTAs/SM, flip-encoded atomicMax partial
// maxima, A.A^T triangular symmetry with column-max scatter.
// R15 = R9 base (best measured, separate finalize; fused tail dropped for
// good) with ONE change: KC 32 -> 64, halving stage count (8 -> 4) and thus
// barrier/wait serialization events, doubling uninterrupted compute runs.
// ---------------------------------------------------------------------------

#define BB    4096
#define DD    256
#define KC    64           // K elems per stage
#define NSTG  4            // 256/64
#define PITCH 144          // smem row pitch bytes (128 data + 16 pad)
#define NTRI  528          // upper-tri tiles for matrix 0 (32*33/2)
#define NBLK  (NTRI + 2 * 1024)

__device__ __align__(16) __half g_X[(size_t)3 * BB * DD];   // [m][row][k]
__device__ unsigned int g_negbits[3 * BB];   // flip-encoded row maxima
__device__ float g_pos[2 * BB];              // positive-pair dots

// smem: labc[128] @0 | labr[128] @512 | stages @1024 (3 x 36864)
#define SM_LABC 0
#define SM_LABR 512
#define SM_STG  1024
#define STG_SZ  36864
#define SM_A(b) (SM_STG + (b) * STG_SZ)
#define SM_B(b) (SM_A(b) + 128 * PITCH)
#define SMEM_TOTAL (SM_STG + 3 * STG_SZ)     // 111616

__device__ __forceinline__ uint32_t smem_u32(const void* p) {
    uint32_t a;
    asm("{ .reg .u64 t; cvta.to.shared.u64 t, %1; cvt.u32.u64 %0, t; }"
        : "=r"(a) : "l"(p));
    return a;
}
#define CP16(dst, src) \
    asm volatile("cp.async.cg.shared.global [%0], [%1], 16;" :: "r"(dst), "l"(src))
#define CP_COMMIT() asm volatile("cp.async.commit_group;" ::: "memory")
#define CP_WAIT(n)  asm volatile("cp.async.wait_group %0;" :: "n"(n) : "memory")
#define LDM4(r, a) \
    asm volatile("ldmatrix.sync.aligned.m8n8.x4.shared.b16 {%0,%1,%2,%3}, [%4];" \
        : "=r"((r)[0]), "=r"((r)[1]), "=r"((r)[2]), "=r"((r)[3]) : "r"(a))
#define MMA(d, a, b0, b1) \
    asm volatile("mma.sync.aligned.m16n8k16.row.col.f32.f16.f16.f32 " \
        "{%0,%1,%2,%3}, {%4,%5,%6,%7}, {%8,%9}, {%0,%1,%2,%3};" \
        : "+f"((d)[0]), "+f"((d)[1]), "+f"((d)[2]), "+f"((d)[3]) \
        : "r"((a)[0]), "r"((a)[1]), "r"((a)[2]), "r"((a)[3]), "r"(b0), "r"(b1))

// monotone float <-> uint encoding for atomicMax over signed floats
__device__ __forceinline__ unsigned int fflip(float f) {
    unsigned int u = __float_as_uint(f);
    return u ^ (unsigned int)(((int)u >> 31) | 0x80000000);
}
__device__ __forceinline__ float funflip(unsigned int m) {
    unsigned int u = (m & 0x80000000u) ? (m ^ 0x80000000u) : ~m;
    return __uint_as_float(u);
}

// --------------------------- normalize -> fp16 (+ negbits init) ------------
__global__ void norm_kernel(const float* __restrict__ anchor,
                            const float* __restrict__ positive) {
    int warp = (blockIdx.x * blockDim.x + threadIdx.x) >> 5;
    int lane = threadIdx.x & 31;
    if (warp >= 3 * BB) return;
    if (lane == 0) g_negbits[warp] = 0u;     // == fflip(very negative)

    const float* src;
    __half2* dst;
    if (warp < BB) {
        src = anchor + (size_t)warp * DD;
        dst = (__half2*)(g_X + (size_t)warp * DD);
    } else {
        int r = warp - BB, i = r >> 1, v = r & 1;   // r = i*2 + v
        src = positive + (size_t)r * DD;
        dst = (__half2*)(g_X + (size_t)((1 + v) * BB + i) * DD);
    }

    const float4* s4 = (const float4*)src;
    float4 x0 = s4[lane], x1 = s4[lane + 32];
    float ss = x0.x*x0.x + x0.y*x0.y + x0.z*x0.z + x0.w*x0.w
             + x1.x*x1.x + x1.y*x1.y + x1.z*x1.z + x1.w*x1.w;
    #pragma unroll
    for (int o = 16; o >= 1; o >>= 1) ss += __shfl_xor_sync(0xffffffffu, ss, o);
    float inv = rsqrtf(fmaxf(ss, 1e-24f));

    dst[2*lane]      = __floats2half2_rn(x0.x*inv, x0.y*inv);
    dst[2*lane + 1]  = __floats2half2_rn(x0.z*inv, x0.w*inv);
    dst[64 + 2*lane] = __floats2half2_rn(x1.x*inv, x1.y*inv);
    dst[65 + 2*lane] = __floats2half2_rn(x1.z*inv, x1.w*inv);
}

// --------------------------- GEMM + masked max (row & col) -----------------
// stage tile: 128 rows x 64 halfs (128B) for A and B each -> 2048 x 16B chunks
__device__ __forceinline__ void load_stage(uint32_t sb, int buf, int s,
                                           int rowbase, int brow, int tid) {
    const char* Xg = (const char*)g_X;
    #pragma unroll
    for (int lp = 0; lp < 4; lp++) {                 // A: 1024 chunks of 16B
        int idx = tid + (lp << 8);
        int row = idx >> 3, ch = idx & 7;
        uint32_t dst = sb + SM_A(buf) + row * PITCH + ch * 16;
        const char* src = Xg + (size_t)(rowbase + row) * (DD * 2) + s * 128 + ch * 16;
        CP16(dst, src);
    }
    #pragma unroll
    for (int lp = 0; lp < 4; lp++) {                 // B: 1024 chunks of 16B
        int idx = tid + (lp << 8);
        int row = idx >> 3, ch = idx & 7;
        uint32_t dst = sb + SM_B(buf) + row * PITCH + ch * 16;
        const char* src = Xg + (size_t)(brow + row) * (DD * 2) + s * 128 + ch * 16;
        CP16(dst, src);
    }
    CP_COMMIT();
}

__global__ __launch_bounds__(256, 2)
void gemm_max_kernel(const int* __restrict__ labels) {
    extern __shared__ char smem[];
    uint32_t sb = smem_u32(smem);
    int* labc = (int*)(smem + SM_LABC);
    int* labr = (int*)(smem + SM_LABR);

    const int tid = threadIdx.x;
    const int lane = tid & 31;
    const int wid = tid >> 5;
    const int wm = wid >> 2, wn = wid & 3;           // 2 x 4 warp grid

    // ---- decode (m, rt, ct) from linear block id (closed form) ----
    int bid = blockIdx.x;
    int m, rt, ct;
    if (bid < NTRI) {
        m = 0;
        float bf = (float)bid;
        int r = (int)floorf(32.5f - sqrtf(32.5f * 32.5f - 2.0f * bf));
        int off = (r * (65 - r)) >> 1;
        if (off > bid)          { r--; off = (r * (65 - r)) >> 1; }
        else if (off + (32 - r) <= bid) { r++; off = (r * (65 - r)) >> 1; }
        rt = r;
        ct = r + (bid - off);
    } else {
        int t = bid - NTRI;
        m = 1 + (t >> 10);
        rt = (t & 1023) >> 5;
        ct = t & 31;
    }
    const int rowbase = rt << 7;
    const int cibase  = ct << 7;                     // col base within matrix
    const int brow    = m * BB + cibase;             // B rows in g_X

    if (tid < 128) {
        labc[tid] = labels[cibase + tid];
        labr[tid] = labels[rowbase + tid];
    }

    float acc[4][4][4];                              // [mi][ni][frag]
    #pragma unroll
    for (int i = 0; i < 4; i++)
        #pragma unroll
        for (int j = 0; j < 4; j++)
            #pragma unroll
            for (int k = 0; k < 4; k++) acc[i][j][k] = 0.f;

    load_stage(sb, 0, 0, rowbase, brow, tid);
    load_stage(sb, 1, 1, rowbase, brow, tid);

    // warp tile 64x32: A rows wm*64 + mi*16, B cols wn*32 + ni2*16
    const uint32_t a_off = (wm * 64 + (lane & 15)) * PITCH + ((lane >> 4) & 1) * 16;
    const uint32_t b_off = (wn * 32 + (lane & 7) + ((lane >> 4) & 1) * 8) * PITCH
                         + ((lane >> 3) & 1) * 16;

    for (int s = 0; s < NSTG; s++) {
        int buf = s % 3;
        CP_WAIT(1);
        __syncthreads();

        uint32_t ab = sb + SM_A(buf) + a_off;
        uint32_t bb = sb + SM_B(buf) + b_off;
        #pragma unroll
        for (int ks = 0; ks < 4; ks++) {             // 4 x K=16 within KC=64
            uint32_t af[4][4];
            #pragma unroll
            for (int mi = 0; mi < 4; mi++)
                LDM4(af[mi], ab + ks * 32 + mi * 16 * PITCH);
            #pragma unroll
            for (int ni2 = 0; ni2 < 2; ni2++) {
                uint32_t bf[4];
                LDM4(bf, bb + ks * 32 + ni2 * 16 * PITCH);
                #pragma unroll
                for (int mi = 0; mi < 4; mi++) {
                    MMA(acc[mi][2*ni2],   af[mi], bf[0], bf[1]);
                    MMA(acc[mi][2*ni2+1], af[mi], bf[2], bf[3]);
                }
            }
        }
        __syncthreads();
        if (s + 2 < NSTG)
            load_stage(sb, (s + 2) % 3, s + 2, rowbase, brow, tid);
    }

    // ------- epilogue 1: per-row masked max (+ diagonal positives) ---------
    #pragma unroll
    for (int mi = 0; mi < 4; mi++) {
        #pragma unroll
        for (int hi = 0; hi < 2; hi++) {
            int lr = wm * 64 + mi * 16 + hi * 8 + (lane >> 2);
            int rlab = labr[lr];
            int grow = rowbase + lr;
            float mx = -1e30f, pv = 0.f;
            int match = 0;
            #pragma unroll
            for (int ni = 0; ni < 4; ni++) {
                int c = wn * 32 + ni * 8 + 2 * (lane & 3);
                float v0 = acc[mi][ni][hi * 2 + 0];
                float v1 = acc[mi][ni][hi * 2 + 1];
                if (labc[c]     != rlab) mx = fmaxf(mx, v0);
                if (labc[c + 1] != rlab) mx = fmaxf(mx, v1);
                if (m > 0) {
                    if (cibase + c == grow)     { pv += v0; match = 1; }
                    if (cibase + c + 1 == grow) { pv += v1; match = 1; }
                }
            }
            mx = fmaxf(mx, __shfl_xor_sync(0xffffffffu, mx, 1));
            mx = fmaxf(mx, __shfl_xor_sync(0xffffffffu, mx, 2));
            pv += __shfl_xor_sync(0xffffffffu, pv, 1);
            pv += __shfl_xor_sync(0xffffffffu, pv, 2);
            match |= __shfl_xor_sync(0xffffffffu, match, 1);
            match |= __shfl_xor_sync(0xffffffffu, match, 2);
            if ((lane & 3) == 0) {
                atomicMax(&g_negbits[m * BB + grow], fflip(mx));
                if (m > 0 && match) g_pos[(m - 1) * BB + grow] = pv;
            }
        }
    }

    // ------- epilogue 2 (m=0 off-diagonal): per-column masked max ----------
    if (m == 0 && rt != ct) {
        #pragma unroll
        for (int ni = 0; ni < 4; ni++) {
            int c = wn * 32 + ni * 8 + 2 * (lane & 3);
            int cl0 = labc[c], cl1 = labc[c + 1];
            float cm0 = -1e30f, cm1 = -1e30f;
            #pragma unroll
            for (int mi = 0; mi < 4; mi++) {
                #pragma unroll
                for (int hi = 0; hi < 2; hi++) {
                    int lr = wm * 64 + mi * 16 + hi * 8 + (lane >> 2);
                    int rl = labr[lr];
                    float v0 = acc[mi][ni][hi * 2 + 0];
                    float v1 = acc[mi][ni][hi * 2 + 1];
                    if (rl != cl0) cm0 = fmaxf(cm0, v0);
                    if (rl != cl1) cm1 = fmaxf(cm1, v1);
                }
            }
            #pragma unroll
            for (int o = 4; o <= 16; o <<= 1) {
                cm0 = fmaxf(cm0, __shfl_xor_sync(0xffffffffu, cm0, o));
                cm1 = fmaxf(cm1, __shfl_xor_sync(0xffffffffu, cm1, o));
            }
            if (lane < 4) {
                atomicMax(&g_negbits[cibase + c],     fflip(cm0));
                atomicMax(&g_negbits[cibase + c + 1], fflip(cm1));
            }
        }
    }
}

// ------------------- fused finalize + deterministic reduce -----------------
__global__ __launch_bounds__(1024, 1)
void finalize_reduce_kernel(float* __restrict__ out) {
    __shared__ float s[1024];
    float tot = 0.f;
    #pragma unroll
    for (int r = 0; r < 4; r++) {
        int i = threadIdx.x + (r << 10);
        float ma = funflip(g_negbits[i]);
        float m0 = funflip(g_negbits[BB + i]);
        float m1 = funflip(g_negbits[2 * BB + i]);
        float d0 = g_pos[i], d1 = g_pos[BB + i];
        float neg0 = sqrtf(fmaxf(2.f - 2.f * fmaxf(ma, m0), 1e-12f));
        float neg1 = sqrtf(fmaxf(2.f - 2.f * fmaxf(ma, m1), 1e-12f));
        float pos0 = sqrtf(fmaxf(2.f - 2.f * d0, 1e-12f));
        float pos1 = sqrtf(fmaxf(2.f - 2.f * d1, 1e-12f));
        tot += fmaxf(pos0 - neg0 + 1.0f, 0.0f) + fmaxf(pos1 - neg1 + 1.0f, 0.0f);
    }
    s[threadIdx.x] = tot;
    __syncthreads();
    #pragma unroll
    for (int o = 512; o >= 1; o >>= 1) {
        if (threadIdx.x < o) s[threadIdx.x] += s[threadIdx.x + o];
        __syncthreads();
    }
    if (threadIdx.x == 0) out[0] = s[0] * (1.0f / (2.0f * BB));
}

// ---------------------------------------------------------------------------
extern "C" void kernel_launch(void* const* d_in, const int* in_sizes, int n_in,
                              void* d_out, int out_size) {
    const float* anchor = nullptr;
    const float* positive = nullptr;
    const int*   labels = nullptr;
    for (int i = 0; i < n_in; i++) {
        if (in_sizes[i] == BB * DD)          anchor   = (const float*)d_in[i];
        else if (in_sizes[i] == 2 * BB * DD) positive = (const float*)d_in[i];
        else if (in_sizes[i] == BB)          labels   = (const int*)d_in[i];
    }

    norm_kernel<<<1536, 256>>>(anchor, positive);

    cudaFuncSetAttribute(gemm_max_kernel,
                         cudaFuncAttributeMaxDynamicSharedMemorySize, SMEM_TOTAL);
    gemm_max_kernel<<<NBLK, 256, SMEM_TOTAL>>>(labels);

    finalize_reduce_kernel<<<1, 1024>>>((float*)d_out);
}